// round 5
// baseline (speedup 1.0000x reference)
#include <cuda_runtime.h>
#include <cuda_bf16.h>
#include <cstdint>

#define Nn 307
#define Cc 64
#define Tt 12
#define BT 96
#define NPAD 320
#define KC 192

// ---------------- scratch ----------------
__device__ float g_A[Cc * Cc];
__device__ float g_u[Cc], g_v[Cc];
__device__ float g_cconst[1];
__device__ float g_xu[BT * NPAD];
__device__ float g_xv[BT * NPAD];
__device__ __nv_bfloat16 g_Y[(size_t)BT * NPAD * KC];   // [Yhi | Yhi | Ylo]
__device__ __nv_bfloat16 g_X[(size_t)BT * NPAD * KC];   // [Xhi | Xlo | Xhi]

__device__ __forceinline__ uint32_t smem_u32(const void* p) {
    uint32_t a;
    asm("{ .reg .u64 t; cvta.to.shared.u64 t, %1; cvt.u32.u64 %0, t; }" : "=r"(a) : "l"(p));
    return a;
}

// ---------------- P0: A = Wq^T Wk (scaled), u, v, c — parallel ----------------
__global__ void p0_kernel(const float* __restrict__ Wq, const float* __restrict__ bq,
                          const float* __restrict__ Wk, const float* __restrict__ bk)
{
    const float s = 0.35355339059327373f;   // 1/sqrt(8)
    int blk = blockIdx.x, tid = threadIdx.x;
    if (blk < 16) {
        int gid = blk * 256 + tid;          // one element of A per thread
        int c = gid >> 6, d = gid & 63;
        float a = 0.f;
        #pragma unroll 8
        for (int e = 0; e < 64; e++) a += Wq[e * 64 + c] * Wk[e * 64 + d];
        g_A[gid] = a * s;
    } else {
        if (tid < 64) {
            float ua = 0.f;
            #pragma unroll 8
            for (int e = 0; e < 64; e++) ua += Wq[e * 64 + tid] * bk[e];
            g_u[tid] = ua * s;
        } else if (tid < 128) {
            int d = tid - 64;
            float va = 0.f;
            #pragma unroll 8
            for (int e = 0; e < 64; e++) va += Wk[e * 64 + d] * bq[e];
            g_v[d] = va * s;
        } else if (tid == 128) {
            float ca = 0.f;
            #pragma unroll 8
            for (int e = 0; e < 64; e++) ca += bq[e] * bk[e];
            g_cconst[0] = ca * s;
        }
    }
}

// ---------------- P1: Y = x·A; bf16 splits; xu/xv ----------------
#define P1_SMEM_FLOATS (64 * 128 + 64 * 64 + 128)

__global__ void __launch_bounds__(256, 1)
p1_kernel(const float* __restrict__ x)
{
    extern __shared__ float sm[];
    float* xs  = sm;               // [c][n], stride 128
    float* As  = sm + 64 * 128;
    float* uvs = As + 64 * 64;

    int bt = blockIdx.x, rt = blockIdx.y;
    int b = bt / Tt, t = bt % Tt;
    int n0 = rt * 128;
    int tid = threadIdx.x;

    const float* xb = x + ((size_t)(b * Cc) * Tt + t) * Nn;
    for (int i = tid; i < 64 * 128; i += 256) {
        int c = i >> 7, n = i & 127;
        int ng = n0 + n;
        xs[i] = (ng < Nn) ? xb[(size_t)c * (Tt * Nn) + ng] : 0.f;
    }
    for (int i = tid; i < 64 * 64; i += 256) As[i] = g_A[i];
    if (tid < 64) uvs[tid] = g_u[tid];
    else if (tid < 128) uvs[tid] = g_v[tid - 64];
    __syncthreads();

    int e0  = (tid & 7) * 8;
    int r0l = (tid >> 3) * 4;
    float acc[4][8] = {};
    #pragma unroll 8
    for (int c = 0; c < 64; c++) {
        float4 a0 = *(const float4*)&As[c * 64 + e0];
        float4 a1 = *(const float4*)&As[c * 64 + e0 + 4];
        float4 x4 = *(const float4*)&xs[c * 128 + r0l];
        float av[8] = {a0.x, a0.y, a0.z, a0.w, a1.x, a1.y, a1.z, a1.w};
        float xv4[4] = {x4.x, x4.y, x4.z, x4.w};
        #pragma unroll
        for (int j = 0; j < 4; j++)
            #pragma unroll
            for (int e = 0; e < 8; e++)
                acc[j][e] += xv4[j] * av[e];
    }

    #pragma unroll
    for (int j = 0; j < 4; j++) {
        int row = n0 + r0l + j;
        if (row < NPAD) {
            __nv_bfloat16* yr = g_Y + ((size_t)bt * NPAD + row) * KC;
            #pragma unroll
            for (int i = 0; i < 4; i++) {
                float v0 = acc[j][2 * i], v1 = acc[j][2 * i + 1];
                __nv_bfloat16 h0 = __float2bfloat16(v0);
                __nv_bfloat16 h1 = __float2bfloat16(v1);
                __nv_bfloat16 l0 = __float2bfloat16(v0 - __bfloat162float(h0));
                __nv_bfloat16 l1 = __float2bfloat16(v1 - __bfloat162float(h1));
                __nv_bfloat162 hh; hh.x = h0; hh.y = h1;
                __nv_bfloat162 ll; ll.x = l0; ll.y = l1;
                int col = e0 + 2 * i;
                *(__nv_bfloat162*)(yr + col)       = hh;
                *(__nv_bfloat162*)(yr + 64 + col)  = hh;
                *(__nv_bfloat162*)(yr + 128 + col) = ll;
            }
        }
    }
    #pragma unroll
    for (int j = 0; j < 4; j++) {
        int row = n0 + r0l + j;
        if (row < NPAD) {
            __nv_bfloat16* xr = g_X + ((size_t)bt * NPAD + row) * KC;
            #pragma unroll
            for (int i = 0; i < 4; i++) {
                int c = e0 + 2 * i;
                float v0 = xs[c * 128 + r0l + j];
                float v1 = xs[(c + 1) * 128 + r0l + j];
                __nv_bfloat16 h0 = __float2bfloat16(v0);
                __nv_bfloat16 h1 = __float2bfloat16(v1);
                __nv_bfloat16 l0 = __float2bfloat16(v0 - __bfloat162float(h0));
                __nv_bfloat16 l1 = __float2bfloat16(v1 - __bfloat162float(h1));
                __nv_bfloat162 hh; hh.x = h0; hh.y = h1;
                __nv_bfloat162 ll; ll.x = l0; ll.y = l1;
                *(__nv_bfloat162*)(xr + c)        = hh;
                *(__nv_bfloat162*)(xr + 64 + c)   = ll;
                *(__nv_bfloat162*)(xr + 128 + c)  = hh;
            }
        }
    }

    if (tid < 128) {
        int r = tid, ng = n0 + r;
        if (ng < NPAD) {
            float a = 0.f;
            for (int c = 0; c < 64; c++) a += xs[c * 128 + r] * uvs[c];
            g_xu[bt * NPAD + ng] = a;
        }
    } else {
        int r = tid - 128, ng = n0 + r;
        if (ng < NPAD) {
            float a = 0.f;
            for (int c = 0; c < 64; c++) a += xs[c * 128 + r] * uvs[64 + c];
            g_xv[bt * NPAD + ng] = a + g_cconst[0];
        }
    }
}

// ---------------- Main: persistent per-bt, mma.sync + register softmax ----------------
#define ROWB 24                      // 16B chunks per 192-bf16 row
#define SM_X  0                      // 320*24*16 = 122880
#define SM_Y  122880                 // 64*24*16  = 24576
#define SM_PM 147456                 // 64*4 floats
#define SM_PS 148480                 // 64*4 floats
#define SM_TOT 149504

#define LDSM4(r0_, r1_, r2_, r3_, addr) \
    asm volatile("ldmatrix.sync.aligned.m8n8.x4.shared.b16 {%0,%1,%2,%3}, [%4];" \
        : "=r"(r0_), "=r"(r1_), "=r"(r2_), "=r"(r3_) : "r"(addr))

#define MMA16816(d, a, b) \
    asm volatile("mma.sync.aligned.m16n8k16.row.col.f32.bf16.bf16.f32 " \
        "{%0,%1,%2,%3}, {%4,%5,%6,%7}, {%8,%9}, {%0,%1,%2,%3};" \
        : "+f"((d)[0]), "+f"((d)[1]), "+f"((d)[2]), "+f"((d)[3]) \
        : "r"((a)[0]), "r"((a)[1]), "r"((a)[2]), "r"((a)[3]), "r"((b)[0]), "r"((b)[1]))

__global__ void __launch_bounds__(256, 1)
attn_mma_kernel(const int* __restrict__ mask, float* __restrict__ out)
{
    extern __shared__ char smc[];
    int tid = threadIdx.x, wid = tid >> 5, lane = tid & 31;
    int bt = blockIdx.x;
    int b = bt / Tt;

    // ---- load full X slab once (swizzled) ----
    {
        const uint4* xsrc = (const uint4*)(g_X + (size_t)bt * NPAD * KC);
        uint4* xd = (uint4*)(smc + SM_X);
        for (int i = tid; i < NPAD * ROWB; i += 256) {
            int row = i / ROWB, ci = i - row * ROWB;
            xd[row * ROWB + (ci ^ (row & 7))] = xsrc[i];
        }
    }

    int wr = wid >> 2, wc = wid & 3;
    int m0w = wr * 32, n0w = wc * 80;
    uint32_t smbY = smem_u32(smc + SM_Y);
    uint32_t smbX = smem_u32(smc + SM_X);
    float* pm = (float*)(smc + SM_PM);
    float* ps = (float*)(smc + SM_PS);

    // per-warp constant column bias terms
    float xvA[10], xvB[10];
    #pragma unroll
    for (int ni = 0; ni < 10; ni++) {
        int col = n0w + (lane & 3) * 2 + ni * 8;
        xvA[ni] = g_xv[bt * NPAD + col];
        xvB[ni] = g_xv[bt * NPAD + col + 1];
    }

    // ldmatrix row addresses
    int aRowL[2], bRow[5];
    #pragma unroll
    for (int mi = 0; mi < 2; mi++)
        aRowL[mi] = m0w + mi * 16 + ((lane >> 3) & 1) * 8 + (lane & 7);
    #pragma unroll
    for (int pi = 0; pi < 5; pi++)
        bRow[pi] = n0w + pi * 16 + (lane >> 4) * 8 + (lane & 7);
    int aChf = lane >> 4;
    int bChf = (lane >> 3) & 1;

    for (int mt = 0; mt < 5; mt++) {
        int r0 = mt * 64;
        // ---- load Y tile (safe: all prior GEMM reads completed before last sync) ----
        {
            const uint4* ysrc = (const uint4*)(g_Y + ((size_t)bt * NPAD + r0) * KC);
            uint4* yd = (uint4*)(smc + SM_Y);
            for (int i = tid; i < 64 * ROWB; i += 256) {
                int row = i / ROWB, ci = i - row * ROWB;
                yd[row * ROWB + (ci ^ (row & 7))] = ysrc[i];
            }
        }
        __syncthreads();

        // ---- GEMM 64x320x192 ----
        float acc[2][10][4];
        #pragma unroll
        for (int mi = 0; mi < 2; mi++)
            #pragma unroll
            for (int ni = 0; ni < 10; ni++)
                #pragma unroll
                for (int q = 0; q < 4; q++) acc[mi][ni][q] = 0.f;

        #pragma unroll
        for (int kk = 0; kk < 12; kk++) {
            int c0 = kk * 2;
            uint32_t a[2][4], bf[5][4];
            #pragma unroll
            for (int mi = 0; mi < 2; mi++) {
                int r = aRowL[mi];
                uint32_t ad = smbY + r * 384 + (((c0 + aChf) ^ (r & 7)) << 4);
                LDSM4(a[mi][0], a[mi][1], a[mi][2], a[mi][3], ad);
            }
            #pragma unroll
            for (int pi = 0; pi < 5; pi++) {
                int r = bRow[pi];
                uint32_t bd = smbX + r * 384 + (((c0 + bChf) ^ (r & 7)) << 4);
                LDSM4(bf[pi][0], bf[pi][1], bf[pi][2], bf[pi][3], bd);
            }
            #pragma unroll
            for (int mi = 0; mi < 2; mi++)
                #pragma unroll
                for (int pi = 0; pi < 5; pi++) {
                    MMA16816(acc[mi][2 * pi],     a[mi], (&bf[pi][0]));
                    MMA16816(acc[mi][2 * pi + 1], a[mi], (&bf[pi][2]));
                }
        }

        // ---- apply mask + bias, per-row max (registers) ----
        #pragma unroll
        for (int mi = 0; mi < 2; mi++) {
            #pragma unroll
            for (int h = 0; h < 2; h++) {
                int nloc = m0w + mi * 16 + (lane >> 2) + h * 8;
                int n = r0 + nloc;
                bool nvalid = n < Nn;
                float xu = 0.f;
                const int* mrow = mask;   // safe dummy base
                if (nvalid) {
                    xu = g_xu[bt * NPAD + n];
                    mrow = mask + ((size_t)b * Nn + n) * Nn;
                }
                float mx = -3.4e38f;
                #pragma unroll
                for (int ni = 0; ni < 10; ni++) {
                    int m0c = n0w + ni * 8 + (lane & 3) * 2;
                    float s0 = -1e9f, s1 = -1e9f;
                    if (nvalid) {
                        if (m0c < Nn && mrow[m0c])
                            s0 = acc[mi][ni][h * 2] + xu + xvA[ni];
                        if (m0c + 1 < Nn && mrow[m0c + 1])
                            s1 = acc[mi][ni][h * 2 + 1] + xu + xvB[ni];
                    }
                    acc[mi][ni][h * 2]     = s0;
                    acc[mi][ni][h * 2 + 1] = s1;
                    mx = fmaxf(mx, fmaxf(s0, s1));
                }
                mx = fmaxf(mx, __shfl_xor_sync(0xffffffffu, mx, 1));
                mx = fmaxf(mx, __shfl_xor_sync(0xffffffffu, mx, 2));
                if ((lane & 3) == 0) pm[nloc * 4 + wc] = mx;
            }
        }
        __syncthreads();

        // ---- exp + per-row sum ----
        #pragma unroll
        for (int mi = 0; mi < 2; mi++) {
            #pragma unroll
            for (int h = 0; h < 2; h++) {
                int nloc = m0w + mi * 16 + (lane >> 2) + h * 8;
                float4 p = *(float4*)&pm[nloc * 4];
                float M = fmaxf(fmaxf(p.x, p.y), fmaxf(p.z, p.w));
                float sum = 0.f;
                #pragma unroll
                for (int ni = 0; ni < 10; ni++) {
                    float e0 = __expf(acc[mi][ni][h * 2]     - M);
                    float e1 = __expf(acc[mi][ni][h * 2 + 1] - M);
                    acc[mi][ni][h * 2]     = e0;
                    acc[mi][ni][h * 2 + 1] = e1;
                    sum += e0 + e1;
                }
                sum += __shfl_xor_sync(0xffffffffu, sum, 1);
                sum += __shfl_xor_sync(0xffffffffu, sum, 2);
                if ((lane & 3) == 0) ps[nloc * 4 + wc] = sum;
            }
        }
        __syncthreads();

        // ---- normalize + store ----
        #pragma unroll
        for (int mi = 0; mi < 2; mi++) {
            #pragma unroll
            for (int h = 0; h < 2; h++) {
                int nloc = m0w + mi * 16 + (lane >> 2) + h * 8;
                int n = r0 + nloc;
                if (n >= Nn) continue;
                float4 q = *(float4*)&ps[nloc * 4];
                float inv = 1.0f / (q.x + q.y + q.z + q.w);
                float* orow = out + ((size_t)bt * Nn + n) * Nn;
                #pragma unroll
                for (int ni = 0; ni < 10; ni++) {
                    int m = n0w + ni * 8 + (lane & 3) * 2;
                    if (m < Nn)     orow[m]     = acc[mi][ni][h * 2]     * inv;
                    if (m + 1 < Nn) orow[m + 1] = acc[mi][ni][h * 2 + 1] * inv;
                }
            }
        }
        __syncthreads();
    }
}

extern "C" void kernel_launch(void* const* d_in, const int* in_sizes, int n_in,
                              void* d_out, int out_size)
{
    const float* x    = (const float*)d_in[0];
    const int*   mask = (const int*)  d_in[1];
    const float* Wq   = (const float*)d_in[2];
    const float* bq   = (const float*)d_in[3];
    const float* Wk   = (const float*)d_in[4];
    const float* bk   = (const float*)d_in[5];
    float* out = (float*)d_out;

    cudaFuncSetAttribute(p1_kernel, cudaFuncAttributeMaxDynamicSharedMemorySize,
                         P1_SMEM_FLOATS * (int)sizeof(float));
    cudaFuncSetAttribute(attn_mma_kernel, cudaFuncAttributeMaxDynamicSharedMemorySize, SM_TOT);

    p0_kernel<<<17, 256>>>(Wq, bq, Wk, bk);
    p1_kernel<<<dim3(BT, 3), 256, P1_SMEM_FLOATS * sizeof(float)>>>(x);
    attn_mma_kernel<<<BT, 256, SM_TOT>>>(mask, out);
}

// round 6
// speedup vs baseline: 1.9237x; 1.9237x over previous
#include <cuda_runtime.h>
#include <cuda_bf16.h>
#include <cstdint>

#define Nn 307
#define Cc 64
#define Tt 12
#define BT 96
#define NPAD 320
#define XC 128            // cols in split buffers: [hi(64) | lo(64)]

// ---------------- scratch ----------------
__device__ float g_A[Cc * Cc];
__device__ float g_u[Cc], g_v[Cc];
__device__ float g_cconst[1];
__device__ float g_xu[BT * NPAD];
__device__ float g_xv[BT * NPAD];
__device__ __nv_bfloat16 g_Y[(size_t)BT * NPAD * XC];   // [Yhi | Ylo], 256B/row
__device__ __nv_bfloat16 g_X[(size_t)BT * NPAD * XC];   // [Xhi | Xlo]

__device__ __forceinline__ uint32_t smem_u32(const void* p) {
    uint32_t a;
    asm("{ .reg .u64 t; cvta.to.shared.u64 t, %1; cvt.u32.u64 %0, t; }" : "=r"(a) : "l"(p));
    return a;
}

// ---------------- P0 ----------------
__global__ void p0_kernel(const float* __restrict__ Wq, const float* __restrict__ bq,
                          const float* __restrict__ Wk, const float* __restrict__ bk)
{
    const float s = 0.35355339059327373f;   // 1/sqrt(8)
    int blk = blockIdx.x, tid = threadIdx.x;
    if (blk < 16) {
        int gid = blk * 256 + tid;
        int c = gid >> 6, d = gid & 63;
        float a = 0.f;
        #pragma unroll 8
        for (int e = 0; e < 64; e++) a += Wq[e * 64 + c] * Wk[e * 64 + d];
        g_A[gid] = a * s;
    } else {
        if (tid < 64) {
            float ua = 0.f;
            #pragma unroll 8
            for (int e = 0; e < 64; e++) ua += Wq[e * 64 + tid] * bk[e];
            g_u[tid] = ua * s;
        } else if (tid < 128) {
            int d = tid - 64;
            float va = 0.f;
            #pragma unroll 8
            for (int e = 0; e < 64; e++) va += Wk[e * 64 + d] * bq[e];
            g_v[d] = va * s;
        } else if (tid == 128) {
            float ca = 0.f;
            #pragma unroll 8
            for (int e = 0; e < 64; e++) ca += bq[e] * bk[e];
            g_cconst[0] = ca * s;
        }
    }
}

// ---------------- P1: Y = x·A; splits; xu/xv; coalesced staged writes ----------------
// smem floats: xs 8192 | As 4096 | uvs 128 | stg (bf16 128x128 = 8192 floats)
#define P1_STG_OFF 12416
#define P1_SMEM_FLOATS (12416 + 8192)

__global__ void __launch_bounds__(256, 2)
p1_kernel(const float* __restrict__ x)
{
    extern __shared__ float sm[];
    float* xs  = sm;               // [c][n], stride 128
    float* As  = sm + 8192;
    float* uvs = sm + 12288;
    __nv_bfloat162* stg = (__nv_bfloat162*)(sm + P1_STG_OFF);  // [row][64 pairs]

    int bt = blockIdx.x, rt = blockIdx.y;
    int b = bt / Tt, t = bt % Tt;
    int n0 = rt * 128;
    int tid = threadIdx.x;
    int nrows = NPAD - n0; if (nrows > 128) nrows = 128;

    const float* xb = x + ((size_t)(b * Cc) * Tt + t) * Nn;
    for (int i = tid; i < 64 * 128; i += 256) {
        int c = i >> 7, n = i & 127;
        int ng = n0 + n;
        xs[i] = (ng < Nn) ? xb[(size_t)c * (Tt * Nn) + ng] : 0.f;
    }
    for (int i = tid; i < 64 * 64; i += 256) As[i] = g_A[i];
    if (tid < 64) uvs[tid] = g_u[tid];
    else if (tid < 128) uvs[tid] = g_v[tid - 64];
    __syncthreads();

    int e0  = (tid & 7) * 8;
    int r0l = (tid >> 3) * 4;
    float acc[4][8] = {};
    #pragma unroll 8
    for (int c = 0; c < 64; c++) {
        float4 a0 = *(const float4*)&As[c * 64 + e0];
        float4 a1 = *(const float4*)&As[c * 64 + e0 + 4];
        float4 x4 = *(const float4*)&xs[c * 128 + r0l];
        float av[8] = {a0.x, a0.y, a0.z, a0.w, a1.x, a1.y, a1.z, a1.w};
        float xv4[4] = {x4.x, x4.y, x4.z, x4.w};
        #pragma unroll
        for (int j = 0; j < 4; j++)
            #pragma unroll
            for (int e = 0; e < 8; e++)
                acc[j][e] += xv4[j] * av[e];
    }

    // xu / xv
    if (tid < 128) {
        int r = tid, ng = n0 + r;
        if (ng < NPAD) {
            float a = 0.f;
            #pragma unroll 8
            for (int c = 0; c < 64; c++) a += xs[c * 128 + r] * uvs[c];
            g_xu[bt * NPAD + ng] = a;
        }
    } else {
        int r = tid - 128, ng = n0 + r;
        if (ng < NPAD) {
            float a = 0.f;
            #pragma unroll 8
            for (int c = 0; c < 64; c++) a += xs[c * 128 + r] * uvs[64 + c];
            g_xv[bt * NPAD + ng] = a + g_cconst[0];
        }
    }

    // ---- stage Y ([hi|lo]) ----
    #pragma unroll
    for (int j = 0; j < 4; j++) {
        int row = r0l + j;
        #pragma unroll
        for (int i = 0; i < 4; i++) {
            float v0 = acc[j][2 * i], v1 = acc[j][2 * i + 1];
            __nv_bfloat16 h0 = __float2bfloat16(v0);
            __nv_bfloat16 h1 = __float2bfloat16(v1);
            __nv_bfloat16 l0 = __float2bfloat16(v0 - __bfloat162float(h0));
            __nv_bfloat16 l1 = __float2bfloat16(v1 - __bfloat162float(h1));
            __nv_bfloat162 hh; hh.x = h0; hh.y = h1;
            __nv_bfloat162 ll; ll.x = l0; ll.y = l1;
            int pc = (e0 + 2 * i) >> 1;
            stg[row * 64 + pc]      = hh;
            stg[row * 64 + 32 + pc] = ll;
        }
    }
    __syncthreads();
    {
        uint4* gy = (uint4*)(g_Y + ((size_t)bt * NPAD + n0) * XC);
        const uint4* s4 = (const uint4*)stg;
        for (int i = tid; i < nrows * 16; i += 256) gy[i] = s4[i];
    }
    __syncthreads();

    // ---- stage X ([hi|lo]) from xs ----
    {
        int r = tid >> 1, h = tid & 1;
        #pragma unroll
        for (int f = h * 32; f < h * 32 + 32; f += 2) {
            float v0 = xs[f * 128 + r];
            float v1 = xs[(f + 1) * 128 + r];
            __nv_bfloat16 h0 = __float2bfloat16(v0);
            __nv_bfloat16 h1 = __float2bfloat16(v1);
            __nv_bfloat16 l0 = __float2bfloat16(v0 - __bfloat162float(h0));
            __nv_bfloat16 l1 = __float2bfloat16(v1 - __bfloat162float(h1));
            __nv_bfloat162 hh; hh.x = h0; hh.y = h1;
            __nv_bfloat162 ll; ll.x = l0; ll.y = l1;
            stg[r * 64 + (f >> 1)]      = hh;
            stg[r * 64 + 32 + (f >> 1)] = ll;
        }
    }
    __syncthreads();
    {
        uint4* gx = (uint4*)(g_X + ((size_t)bt * NPAD + n0) * XC);
        const uint4* s4 = (const uint4*)stg;
        for (int i = tid; i < nrows * 16; i += 256) gx[i] = s4[i];
    }
}

// ---------------- Main: mma.sync GEMM + mask + softmax ----------------
#define ROWB 16              // 16B chunks per 256B row
#define SM_X 0               // 320*256 = 81920
#define SM_Y 81920           // 64*256 = 16384
#define SM_TOT 98304
#define SROW 328

#define LDSM4(r0_, r1_, r2_, r3_, addr) \
    asm volatile("ldmatrix.sync.aligned.m8n8.x4.shared.b16 {%0,%1,%2,%3}, [%4];" \
        : "=r"(r0_), "=r"(r1_), "=r"(r2_), "=r"(r3_) : "r"(addr))

#define MMA16816(d, a, b) \
    asm volatile("mma.sync.aligned.m16n8k16.row.col.f32.bf16.bf16.f32 " \
        "{%0,%1,%2,%3}, {%4,%5,%6,%7}, {%8,%9}, {%0,%1,%2,%3};" \
        : "+f"((d)[0]), "+f"((d)[1]), "+f"((d)[2]), "+f"((d)[3]) \
        : "r"((a)[0]), "r"((a)[1]), "r"((a)[2]), "r"((a)[3]), "r"((b)[0]), "r"((b)[1]))

__global__ void __launch_bounds__(256, 2)
attn_mma_kernel(const int* __restrict__ mask, float* __restrict__ out)
{
    extern __shared__ char smc[];
    int tid = threadIdx.x, wid = tid >> 5, lane = tid & 31;
    int bt = blockIdx.x, mt = blockIdx.y;
    int b = bt / Tt;
    int r0 = mt * 64;

    // ---- load swizzled tiles ----
    {
        const uint4* xsrc = (const uint4*)(g_X + (size_t)bt * NPAD * XC);
        uint4* xd = (uint4*)(smc + SM_X);
        for (int i = tid; i < NPAD * ROWB; i += 256) {
            int row = i >> 4, ci = i & 15;
            xd[(row << 4) + (ci ^ (row & 7))] = xsrc[i];
        }
        const uint4* ysrc = (const uint4*)(g_Y + ((size_t)bt * NPAD + r0) * XC);
        uint4* yd = (uint4*)(smc + SM_Y);
        for (int i = tid; i < 64 * ROWB; i += 256) {
            int row = i >> 4, ci = i & 15;
            yd[(row << 4) + (ci ^ (row & 7))] = ysrc[i];
        }
    }
    __syncthreads();

    int wr = wid >> 2, wc = wid & 3;
    int m0w = wr * 32, n0w = wc * 80;
    uint32_t smbY = smem_u32(smc + SM_Y);
    uint32_t smbX = smem_u32(smc + SM_X);

    int aRowL[2], bRow[5];
    #pragma unroll
    for (int mi = 0; mi < 2; mi++)
        aRowL[mi] = m0w + mi * 16 + ((lane >> 3) & 1) * 8 + (lane & 7);
    #pragma unroll
    for (int pi = 0; pi < 5; pi++)
        bRow[pi] = n0w + pi * 16 + (lane >> 4) * 8 + (lane & 7);
    int aChf = lane >> 4;
    int bChf = (lane >> 3) & 1;

    float acc[2][10][4];
    #pragma unroll
    for (int mi = 0; mi < 2; mi++)
        #pragma unroll
        for (int ni = 0; ni < 10; ni++)
            #pragma unroll
            for (int q = 0; q < 4; q++) acc[mi][ni][q] = 0.f;

    // passes: p=0 hi*hi, p=1 hi*lo, p=2 lo*hi
    #pragma unroll
    for (int kk = 0; kk < 12; kk++) {
        int p = kk >> 2, q = kk & 3;
        int aBase = (p == 2 ? 8 : 0) + q * 2;
        int bBase = (p == 1 ? 8 : 0) + q * 2;
        uint32_t a[2][4], bf[5][4];
        #pragma unroll
        for (int mi = 0; mi < 2; mi++) {
            int r = aRowL[mi];
            uint32_t ad = smbY + (r << 8) + (((aBase + aChf) ^ (r & 7)) << 4);
            LDSM4(a[mi][0], a[mi][1], a[mi][2], a[mi][3], ad);
        }
        #pragma unroll
        for (int pi = 0; pi < 5; pi++) {
            int r = bRow[pi];
            uint32_t bd = smbX + (r << 8) + (((bBase + bChf) ^ (r & 7)) << 4);
            LDSM4(bf[pi][0], bf[pi][1], bf[pi][2], bf[pi][3], bd);
        }
        #pragma unroll
        for (int mi = 0; mi < 2; mi++)
            #pragma unroll
            for (int pi = 0; pi < 5; pi++) {
                MMA16816(acc[mi][2 * pi],     a[mi], (&bf[pi][0]));
                MMA16816(acc[mi][2 * pi + 1], a[mi], (&bf[pi][2]));
            }
    }
    __syncthreads();   // done reading X/Y

    // ---- spill scores ----
    float* S = (float*)(smc);
    {
        int rbase = m0w + (lane >> 2);
        int cbase = n0w + (lane & 3) * 2;
        #pragma unroll
        for (int mi = 0; mi < 2; mi++) {
            #pragma unroll
            for (int ni = 0; ni < 10; ni++) {
                int c = cbase + ni * 8;
                *(float2*)&S[(rbase + mi * 16) * SROW + c]     = make_float2(acc[mi][ni][0], acc[mi][ni][1]);
                *(float2*)&S[(rbase + mi * 16 + 8) * SROW + c] = make_float2(acc[mi][ni][2], acc[mi][ni][3]);
            }
        }
    }
    __syncthreads();

    // ---- softmax (warp per row) ----
    float xv10[10];
    #pragma unroll
    for (int it = 0; it < 10; it++)
        xv10[it] = g_xv[bt * NPAD + lane + it * 32];

    for (int r = wid; r < 64; r += 8) {
        int n = r0 + r;
        if (n >= Nn) break;
        float xun = g_xu[bt * NPAD + n];
        const int* mrow = mask + ((size_t)b * Nn + n) * Nn;
        float v[10];
        float mx = -3.4e38f;
        #pragma unroll
        for (int it = 0; it < 10; it++) {
            int m = lane + it * 32;
            float s = -3.4e38f;
            if (m < Nn) s = mrow[m] ? (S[r * SROW + m] + xun + xv10[it]) : -1e9f;
            v[it] = s;
            mx = fmaxf(mx, s);
        }
        #pragma unroll
        for (int o = 16; o; o >>= 1)
            mx = fmaxf(mx, __shfl_xor_sync(0xffffffffu, mx, o));
        float ssum = 0.f;
        #pragma unroll
        for (int it = 0; it < 10; it++) {
            float e = __expf(v[it] - mx);
            v[it] = e;
            ssum += e;
        }
        #pragma unroll
        for (int o = 16; o; o >>= 1)
            ssum += __shfl_xor_sync(0xffffffffu, ssum, o);
        float inv = 1.0f / ssum;
        float* orow = out + ((size_t)bt * Nn + n) * Nn;
        #pragma unroll
        for (int it = 0; it < 10; it++) {
            int m = lane + it * 32;
            if (m < Nn) orow[m] = v[it] * inv;
        }
    }
}

extern "C" void kernel_launch(void* const* d_in, const int* in_sizes, int n_in,
                              void* d_out, int out_size)
{
    const float* x    = (const float*)d_in[0];
    const int*   mask = (const int*)  d_in[1];
    const float* Wq   = (const float*)d_in[2];
    const float* bq   = (const float*)d_in[3];
    const float* Wk   = (const float*)d_in[4];
    const float* bk   = (const float*)d_in[5];
    float* out = (float*)d_out;

    cudaFuncSetAttribute(p1_kernel, cudaFuncAttributeMaxDynamicSharedMemorySize,
                         P1_SMEM_FLOATS * (int)sizeof(float));
    cudaFuncSetAttribute(attn_mma_kernel, cudaFuncAttributeMaxDynamicSharedMemorySize, SM_TOT);

    p0_kernel<<<17, 256>>>(Wq, bq, Wk, bk);
    p1_kernel<<<dim3(BT, 3), 256, P1_SMEM_FLOATS * sizeof(float)>>>(x);
    attn_mma_kernel<<<dim3(BT, 5), 256, SM_TOT>>>(mask, out);
}